// round 12
// baseline (speedup 1.0000x reference)
#include <cuda_runtime.h>
#include <cuda_bf16.h>
#include <mma.h>
#include <cstdint>

using namespace nvcuda;

#define Bb 2
#define Ss 2048
#define Ee 1024
#define Hh 16
#define Hd 64

// ------------------------- scratch (__device__ globals) ----------------------
__device__ float g_Q1[Bb * Ss * Hd];
__device__ float g_K1[Bb * Ss * Hd];
__device__ float g_V [Bb * Ss * Ee];     // V projection, flat (b, s, e)
__device__ float g_R [Bb * Ss * Ee];     // PV result, row-major (b, q, n)

__device__ __align__(16) __nv_bfloat16 g_xh [Bb * Ss * Ee], g_xl [Bb * Ss * Ee];
__device__ __align__(16) __nv_bfloat16 g_wqh[Ee * Ee],      g_wql[Ee * Ee];
__device__ __align__(16) __nv_bfloat16 g_wkh[Ee * Ee],      g_wkl[Ee * Ee];
__device__ __align__(16) __nv_bfloat16 g_wvh[Ee * Ee],      g_wvl[Ee * Ee];
__device__ __align__(16) __nv_bfloat16 g_woh[Ee * Ee],      g_wol[Ee * Ee];
__device__ __align__(16) __nv_bfloat16 g_q1h[Bb * Ss * Hd], g_q1l[Bb * Ss * Hd];
__device__ __align__(16) __nv_bfloat16 g_k1h[Bb * Ss * Hd], g_k1l[Bb * Ss * Hd];
__device__ __align__(16) __nv_bfloat16 g_Ph [Bb * Ss * Ss], g_Pl [Bb * Ss * Ss];
__device__ __align__(16) __nv_bfloat16 g_vth[Bb * Ee * Ss], g_vtl[Bb * Ee * Ss];
__device__ __align__(16) __nv_bfloat16 g_ah [Bb * Ss * Ee], g_al [Bb * Ss * Ee];

// ---------------------------------------------------------------------------
// Elementwise fp32 -> bf16 hi/lo split (validated round 11).
// ---------------------------------------------------------------------------
__global__ void split_f32(const float4* __restrict__ in, __nv_bfloat162* __restrict__ hi,
                          __nv_bfloat162* __restrict__ lo, int n4)
{
    int i = blockIdx.x * blockDim.x + threadIdx.x;
    if (i >= n4) return;
    float4 v = in[i];
    __nv_bfloat16 h0 = __float2bfloat16(v.x), h1 = __float2bfloat16(v.y);
    __nv_bfloat16 h2 = __float2bfloat16(v.z), h3 = __float2bfloat16(v.w);
    __nv_bfloat16 l0 = __float2bfloat16(v.x - __bfloat162float(h0));
    __nv_bfloat16 l1 = __float2bfloat16(v.y - __bfloat162float(h1));
    __nv_bfloat16 l2 = __float2bfloat16(v.z - __bfloat162float(h2));
    __nv_bfloat16 l3 = __float2bfloat16(v.w - __bfloat162float(h3));
    hi[i * 2]     = __halves2bfloat162(h0, h1);
    hi[i * 2 + 1] = __halves2bfloat162(h2, h3);
    lo[i * 2]     = __halves2bfloat162(l0, l1);
    lo[i * 2 + 1] = __halves2bfloat162(l2, l3);
}

// ---------------------------------------------------------------------------
// wmma split-bf16 NT GEMM, 128x128 tile. Fragment semantics identical to the
// validated kernel (A row_major [m][k] pitch 40, B col_major [n][k] pitch 40).
// Warp grid 2(m) x 4(n); warp tile 64x32 (4x2 frags). Bias pre-loaded into
// accumulators; epilogue stores fragments directly to global.
// C[m,n] = sum_k (Ah+Al)[m,k]*(Bh+Bl)[n,k] + bias[n]  (3-product approx)
// ---------------------------------------------------------------------------
__global__ void __launch_bounds__(256, 2) wsplit_gemm2(
    const __nv_bfloat16* __restrict__ Ah, const __nv_bfloat16* __restrict__ Al, long Az,
    const __nv_bfloat16* __restrict__ Bh, const __nv_bfloat16* __restrict__ Bl, long Bz,
    float* __restrict__ C, long Cz, int ldC,
    const float* __restrict__ bias, int K)
{
    __shared__ __align__(128) __nv_bfloat16 sAh[128][40];
    __shared__ __align__(128) __nv_bfloat16 sAl[128][40];
    __shared__ __align__(128) __nv_bfloat16 sBh[128][40];
    __shared__ __align__(128) __nv_bfloat16 sBl[128][40];

    const int tid = threadIdx.x, wid = tid >> 5;
    const int wm = wid & 1, wn = wid >> 1;
    const int m0 = blockIdx.y * 128, n0 = blockIdx.x * 128;
    Ah += (size_t)blockIdx.z * Az;
    Al += (size_t)blockIdx.z * Az;
    Bh += (size_t)blockIdx.z * Bz;
    Bl += (size_t)blockIdx.z * Bz;
    C  += (size_t)blockIdx.z * Cz;

    wmma::fragment<wmma::accumulator, 16, 16, 16, float> acc[4][2];
    if (bias) {
        // Stage bias (replicated over 16 rows) in the sAh area, init accumulators.
        float* bstage = (float*)sAh;              // 16 x 136 floats = 8704 B < tile
        #pragma unroll
        for (int it = 0; it < 8; ++it) {
            int idx = it * 256 + tid;             // 0 .. 2047
            int r = idx >> 7, c = idx & 127;
            bstage[r * 136 + c] = bias[n0 + c];
        }
        __syncthreads();
        #pragma unroll
        for (int j = 0; j < 2; ++j) {
            wmma::load_matrix_sync(acc[0][j], bstage + wn * 32 + j * 16, 136,
                                   wmma::mem_row_major);
            #pragma unroll
            for (int i = 1; i < 4; ++i) acc[i][j] = acc[0][j];
        }
        __syncthreads();
    } else {
        #pragma unroll
        for (int i = 0; i < 4; ++i)
            #pragma unroll
            for (int j = 0; j < 2; ++j)
                wmma::fill_fragment(acc[i][j], 0.0f);
    }

    const int lrow = tid >> 1, lcb = (tid & 1) * 16;   // 128 rows x 32 cols, 2 uint4/thread

    for (int k0 = 0; k0 < K; k0 += 32) {
        const size_t aoff = (size_t)(m0 + lrow) * K + k0 + lcb;
        const size_t boff = (size_t)(n0 + lrow) * K + k0 + lcb;
        *(uint4*)&sAh[lrow][lcb]     = *(const uint4*)(Ah + aoff);
        *(uint4*)&sAh[lrow][lcb + 8] = *(const uint4*)(Ah + aoff + 8);
        *(uint4*)&sAl[lrow][lcb]     = *(const uint4*)(Al + aoff);
        *(uint4*)&sAl[lrow][lcb + 8] = *(const uint4*)(Al + aoff + 8);
        *(uint4*)&sBh[lrow][lcb]     = *(const uint4*)(Bh + boff);
        *(uint4*)&sBh[lrow][lcb + 8] = *(const uint4*)(Bh + boff + 8);
        *(uint4*)&sBl[lrow][lcb]     = *(const uint4*)(Bl + boff);
        *(uint4*)&sBl[lrow][lcb + 8] = *(const uint4*)(Bl + boff + 8);
        __syncthreads();

        #pragma unroll
        for (int p = 0; p < 3; ++p) {
            const __nv_bfloat16 (*aS)[40] = (p == 2) ? sAl : sAh;
            const __nv_bfloat16 (*bS)[40] = (p == 1) ? sBl : sBh;
            #pragma unroll
            for (int kk = 0; kk < 32; kk += 16) {
                wmma::fragment<wmma::matrix_b, 16, 16, 16, __nv_bfloat16, wmma::col_major> bf[2];
                #pragma unroll
                for (int j = 0; j < 2; ++j)
                    wmma::load_matrix_sync(bf[j], &bS[wn * 32 + j * 16][kk], 40);
                #pragma unroll
                for (int i = 0; i < 4; ++i) {
                    wmma::fragment<wmma::matrix_a, 16, 16, 16, __nv_bfloat16, wmma::row_major> af;
                    wmma::load_matrix_sync(af, &aS[wm * 64 + i * 16][kk], 40);
                    #pragma unroll
                    for (int j = 0; j < 2; ++j)
                        wmma::mma_sync(acc[i][j], af, bf[j], acc[i][j]);
                }
            }
        }
        __syncthreads();
    }

    // Direct-to-global epilogue.
    #pragma unroll
    for (int i = 0; i < 4; ++i)
        #pragma unroll
        for (int j = 0; j < 2; ++j)
            wmma::store_matrix_sync(
                &C[(size_t)(m0 + wm * 64 + i * 16) * ldC + n0 + wn * 32 + j * 16],
                acc[i][j], ldC, wmma::mem_row_major);
}

// ---------------------------------------------------------------------------
// Head-aware V transpose, emitting bf16 hi/lo (validated round 11).
// ---------------------------------------------------------------------------
__global__ void transpose_vh_split(const float* __restrict__ in,
                                   __nv_bfloat16* __restrict__ hiT,
                                   __nv_bfloat16* __restrict__ loT)
{
    __shared__ float t[32][33];
    const int b = blockIdx.z >> 4, h = blockIdx.z & 15;
    const int k0 = blockIdx.x * 32, d0 = blockIdx.y * 32;
    const int tx = threadIdx.x, ty = threadIdx.y;
    const float* src = in + (size_t)b * Ss * Ee + (size_t)h * Ss * Hd;  // (k, d), ld = Hd
    const size_t dbase = (size_t)b * Ee * Ss + (size_t)h * Hd * Ss;     // (d, k), ld = Ss
    #pragma unroll
    for (int i = 0; i < 32; i += 8)
        t[ty + i][tx] = src[(size_t)(k0 + ty + i) * Hd + d0 + tx];
    __syncthreads();
    #pragma unroll
    for (int i = 0; i < 32; i += 8) {
        float v = t[tx][ty + i];
        __nv_bfloat16 hv = __float2bfloat16(v);
        size_t o = dbase + (size_t)(d0 + ty + i) * Ss + k0 + tx;
        hiT[o] = hv;
        loT[o] = __float2bfloat16(v - __bfloat162float(hv));
    }
}

// ---------------------------------------------------------------------------
// Permute PV result R (b, q, n) into flat (b, h, q, d), bf16 hi/lo (validated).
// ---------------------------------------------------------------------------
__global__ void permute_attn_split(const float* __restrict__ R,
                                   __nv_bfloat16* __restrict__ Ahi,
                                   __nv_bfloat16* __restrict__ Alo)
{
    const int idx = blockIdx.x * 256 + threadIdx.x;   // 0 .. Bb*Ss*Ee-1
    const int e = idx & (Ee - 1);
    const int q = (idx >> 10) & (Ss - 1);
    const int b = idx >> 21;
    float v = R[idx];
    __nv_bfloat16 hv = __float2bfloat16(v);
    size_t o = (size_t)b * Ss * Ee + (size_t)(e >> 6) * (Ss * Hd) + (size_t)q * Hd + (e & 63);
    Ahi[o] = hv;
    Alo[o] = __float2bfloat16(v - __bfloat162float(hv));
}

// ---------------------------------------------------------------------------
// Softmax with scale + ALiBi fold: P row holds RAW dot(Q1,K1). Compute
// s = 0.125*raw - slope*|q - k|, softmax over k, write fp32 P + bf16 hi/lo.
// grid = (Ss, Bb), 256 threads.
// ---------------------------------------------------------------------------
__global__ void softmax_alibi_split(float* __restrict__ P, const float* __restrict__ slopes,
                                    __nv_bfloat16* __restrict__ Ph,
                                    __nv_bfloat16* __restrict__ Pl)
{
    const size_t base = (size_t)blockIdx.y * Ss * Ss + (size_t)blockIdx.x * Ss;
    float* r = P + base;
    const int q = blockIdx.x;
    const float slope = slopes[1];
    const int tid = threadIdx.x;
    __shared__ float red[256];

    float vals[8];
    float m = -1e30f;
    #pragma unroll
    for (int i = 0; i < 8; i++) {
        const int k = tid + i * 256;
        vals[i] = 0.125f * r[k] - slope * fabsf((float)(q - k));
        m = fmaxf(m, vals[i]);
    }
    red[tid] = m;
    __syncthreads();
    for (int s = 128; s > 0; s >>= 1) {
        if (tid < s) red[tid] = fmaxf(red[tid], red[tid + s]);
        __syncthreads();
    }
    m = red[0];
    __syncthreads();

    float sum = 0.f;
    #pragma unroll
    for (int i = 0; i < 8; i++) {
        vals[i] = __expf(vals[i] - m);
        sum += vals[i];
    }
    red[tid] = sum;
    __syncthreads();
    for (int s = 128; s > 0; s >>= 1) {
        if (tid < s) red[tid] += red[tid + s];
        __syncthreads();
    }
    const float inv = 1.f / red[0];
    #pragma unroll
    for (int i = 0; i < 8; i++) {
        float v = vals[i] * inv;
        const int k = tid + i * 256;
        r[k] = v;
        __nv_bfloat16 hv = __float2bfloat16(v);
        Ph[base + k] = hv;
        Pl[base + k] = __float2bfloat16(v - __bfloat162float(hv));
    }
}

// ---------------------------------------------------------------------------
extern "C" void kernel_launch(void* const* d_in, const int* in_sizes, int n_in,
                              void* d_out, int out_size)
{
    const float* x      = (const float*)d_in[0];
    const float* bq     = (const float*)d_in[2];
    const float* bk     = (const float*)d_in[4];
    const float* bv     = (const float*)d_in[6];
    const float* bo     = (const float*)d_in[8];
    const float* slopes = (const float*)d_in[9];

    float* out = (float*)d_out;                 // (B, S, E)
    float* P   = out + (long)Bb * Ss * Ee;      // probs1 (B, 1, S, S), computed in place

    float *pQ1, *pK1, *pV, *pR;
    __nv_bfloat16 *pxh, *pxl, *pwqh, *pwql, *pwkh, *pwkl, *pwvh, *pwvl, *pwoh, *pwol;
    __nv_bfloat16 *pq1h, *pq1l, *pk1h, *pk1l, *pPh, *pPl, *pvth, *pvtl, *pah, *pal;
    cudaGetSymbolAddress((void**)&pQ1, g_Q1);
    cudaGetSymbolAddress((void**)&pK1, g_K1);
    cudaGetSymbolAddress((void**)&pV, g_V);
    cudaGetSymbolAddress((void**)&pR, g_R);
    cudaGetSymbolAddress((void**)&pxh, g_xh);
    cudaGetSymbolAddress((void**)&pxl, g_xl);
    cudaGetSymbolAddress((void**)&pwqh, g_wqh);
    cudaGetSymbolAddress((void**)&pwql, g_wql);
    cudaGetSymbolAddress((void**)&pwkh, g_wkh);
    cudaGetSymbolAddress((void**)&pwkl, g_wkl);
    cudaGetSymbolAddress((void**)&pwvh, g_wvh);
    cudaGetSymbolAddress((void**)&pwvl, g_wvl);
    cudaGetSymbolAddress((void**)&pwoh, g_woh);
    cudaGetSymbolAddress((void**)&pwol, g_wol);
    cudaGetSymbolAddress((void**)&pq1h, g_q1h);
    cudaGetSymbolAddress((void**)&pq1l, g_q1l);
    cudaGetSymbolAddress((void**)&pk1h, g_k1h);
    cudaGetSymbolAddress((void**)&pk1l, g_k1l);
    cudaGetSymbolAddress((void**)&pPh, g_Ph);
    cudaGetSymbolAddress((void**)&pPl, g_Pl);
    cudaGetSymbolAddress((void**)&pvth, g_vth);
    cudaGetSymbolAddress((void**)&pvtl, g_vtl);
    cudaGetSymbolAddress((void**)&pah, g_ah);
    cudaGetSymbolAddress((void**)&pal, g_al);

    const int T = 256;
    // Pre-split x and weights to bf16 hi/lo.
    split_f32<<<(Bb * Ss * Ee / 4 + T - 1) / T, T>>>((const float4*)x,
        (__nv_bfloat162*)pxh, (__nv_bfloat162*)pxl, Bb * Ss * Ee / 4);
    split_f32<<<(Ee * Ee / 4 + T - 1) / T, T>>>((const float4*)d_in[1],
        (__nv_bfloat162*)pwqh, (__nv_bfloat162*)pwql, Ee * Ee / 4);
    split_f32<<<(Ee * Ee / 4 + T - 1) / T, T>>>((const float4*)d_in[3],
        (__nv_bfloat162*)pwkh, (__nv_bfloat162*)pwkl, Ee * Ee / 4);
    split_f32<<<(Ee * Ee / 4 + T - 1) / T, T>>>((const float4*)d_in[5],
        (__nv_bfloat162*)pwvh, (__nv_bfloat162*)pwvl, Ee * Ee / 4);
    split_f32<<<(Ee * Ee / 4 + T - 1) / T, T>>>((const float4*)d_in[7],
        (__nv_bfloat162*)pwoh, (__nv_bfloat162*)pwol, Ee * Ee / 4);

    // Head-1 Q/K projections: rows 128..255 per batch of x @ W^T.
    wsplit_gemm2<<<dim3(Ee / 128, 1, Bb), 256>>>(
        pxh + 128 * Ee, pxl + 128 * Ee, (long)Ss * Ee,
        pwqh, pwql, 0, pQ1, (long)128 * Ee, Ee, bq, Ee);
    wsplit_gemm2<<<dim3(Ee / 128, 1, Bb), 256>>>(
        pxh + 128 * Ee, pxl + 128 * Ee, (long)Ss * Ee,
        pwkh, pwkl, 0, pK1, (long)128 * Ee, Ee, bk, Ee);
    // Full V projection (flatten batches: M = 4096).
    wsplit_gemm2<<<dim3(Ee / 128, Bb * Ss / 128, 1), 256>>>(
        pxh, pxl, 0, pwvh, pwvl, 0, pV, 0, Ee, bv, Ee);

    // Split Q1/K1 for the scores GEMM.
    split_f32<<<(Bb * Ss * Hd / 4 + T - 1) / T, T>>>((const float4*)pQ1,
        (__nv_bfloat162*)pq1h, (__nv_bfloat162*)pq1l, Bb * Ss * Hd / 4);
    split_f32<<<(Bb * Ss * Hd / 4 + T - 1) / T, T>>>((const float4*)pK1,
        (__nv_bfloat162*)pk1h, (__nv_bfloat162*)pk1l, Bb * Ss * Hd / 4);

    // Raw scores = Q1 K1^T (GEMM, K = 64); scale+ALiBi+softmax folded next.
    wsplit_gemm2<<<dim3(Ss / 128, Ss / 128, Bb), 256>>>(
        pq1h, pq1l, (long)Ss * Hd, pk1h, pk1l, (long)Ss * Hd,
        P, (long)Ss * Ss, Ss, nullptr, Hd);
    softmax_alibi_split<<<dim3(Ss, Bb), 256>>>(P, slopes, pPh, pPl);

    // Head-aware transpose of V, emitting bf16 hi/lo.
    transpose_vh_split<<<dim3(Ss / 32, Hd / 32, Bb * Hh), dim3(32, 8)>>>(pV, pvth, pvtl);

    // PV: R[b,q,n] = sum_k P[b,q,k] * Vt[b,n,k].
    wsplit_gemm2<<<dim3(Ee / 128, Ss / 128, Bb), 256>>>(
        pPh, pPl, (long)Ss * Ss, pvth, pvtl, (long)Ee * Ss,
        pR, (long)Ss * Ee, Ee, nullptr, Ss);

    // Permute R into flat (b, h, q, d), emitting bf16 hi/lo for the O proj.
    permute_attn_split<<<Bb * Ss * Ee / 256, 256>>>(pR, pah, pal);

    // Output projection.
    wsplit_gemm2<<<dim3(Ee / 128, Bb * Ss / 128, 1), 256>>>(
        pah, pal, 0, pwoh, pwol, 0, out, 0, Ee, bo, Ee);
}

// round 13
// speedup vs baseline: 1.2072x; 1.2072x over previous
#include <cuda_runtime.h>
#include <cuda_bf16.h>
#include <mma.h>
#include <cstdint>

using namespace nvcuda;

#define Bb 2
#define Ss 2048
#define Ee 1024
#define Hh 16
#define Hd 64

// ------------------------- scratch (__device__ globals) ----------------------
__device__ float g_Q1[Bb * Ss * Hd];
__device__ float g_K1[Bb * Ss * Hd];
__device__ float g_V [Bb * Ss * Ee];     // V projection, flat (b, s, e)
__device__ float g_Vt[Bb * Ee * Ss];     // Vt[b][h*64+d][k] = V[b, h, k, d]
__device__ float g_attn[Bb * Ss * Ee];   // attn in flat (b, h, q, d) layout

// ---------------------------------------------------------------------------
// wmma split-bf16 NT GEMM (VALIDATED rounds 6/10). In-kernel hi/lo split.
// C[m,n] = sum_k A[m,k]*B[n,k] + bias[n]
// mode 0: row-major store C[m*ldC+n].
// mode 1: head-flat store (BN=64 == Hd): C[h*Ss*Hd + m*Hd + d], h=(n0+c)>>6.
// ---------------------------------------------------------------------------
__global__ void __launch_bounds__(256) wsplit_gemm(
    const float* __restrict__ A, long Az,
    const float* __restrict__ B, long Bz,
    float* __restrict__ C, long Cz, int ldC,
    const float* __restrict__ bias, int K, int mode)
{
    __shared__ __align__(128) __nv_bfloat16 sAh[64][40];
    __shared__ __align__(128) __nv_bfloat16 sAl[64][40];
    __shared__ __align__(128) __nv_bfloat16 sBh[64][40];
    __shared__ __align__(128) __nv_bfloat16 sBl[64][40];
    __shared__ __align__(128) float sC[64][72];

    const int tid = threadIdx.x, wid = tid >> 5;
    const int wm = wid & 1, wn = wid >> 1;
    const int m0 = blockIdx.y * 64, n0 = blockIdx.x * 64;
    A += (size_t)blockIdx.z * Az;
    B += (size_t)blockIdx.z * Bz;
    C += (size_t)blockIdx.z * Cz;

    const int lrow = tid >> 2, lcb = (tid & 3) * 8;

    wmma::fragment<wmma::accumulator, 16, 16, 16, float> acc[2];
    wmma::fill_fragment(acc[0], 0.0f);
    wmma::fill_fragment(acc[1], 0.0f);

    for (int k0 = 0; k0 < K; k0 += 32) {
        const float* ga = A + (size_t)(m0 + lrow) * K + k0 + lcb;
        const float* gb = B + (size_t)(n0 + lrow) * K + k0 + lcb;
        #pragma unroll
        for (int j = 0; j < 8; j += 4) {
            float4 va = *(const float4*)(ga + j);
            float4 vb = *(const float4*)(gb + j);
            float av[4] = {va.x, va.y, va.z, va.w};
            float bv[4] = {vb.x, vb.y, vb.z, vb.w};
            #pragma unroll
            for (int u = 0; u < 4; ++u) {
                __nv_bfloat16 ha = __float2bfloat16(av[u]);
                sAh[lrow][lcb + j + u] = ha;
                sAl[lrow][lcb + j + u] = __float2bfloat16(av[u] - __bfloat162float(ha));
                __nv_bfloat16 hb = __float2bfloat16(bv[u]);
                sBh[lrow][lcb + j + u] = hb;
                sBl[lrow][lcb + j + u] = __float2bfloat16(bv[u] - __bfloat162float(hb));
            }
        }
        __syncthreads();

        #pragma unroll
        for (int p = 0; p < 3; ++p) {
            const __nv_bfloat16 (*aS)[40] = (p == 2) ? sAl : sAh;
            const __nv_bfloat16 (*bS)[40] = (p == 1) ? sBl : sBh;
            #pragma unroll
            for (int kk = 0; kk < 32; kk += 16) {
                wmma::fragment<wmma::matrix_a, 16, 16, 16, __nv_bfloat16, wmma::row_major> af;
                wmma::fragment<wmma::matrix_b, 16, 16, 16, __nv_bfloat16, wmma::col_major> bf;
                wmma::load_matrix_sync(bf, &bS[wn * 16][kk], 40);
                #pragma unroll
                for (int i = 0; i < 2; ++i) {
                    wmma::load_matrix_sync(af, &aS[wm * 32 + i * 16][kk], 40);
                    wmma::mma_sync(acc[i], af, bf, acc[i]);
                }
            }
        }
        __syncthreads();
    }

    wmma::store_matrix_sync(&sC[wm * 32][wn * 16], acc[0], 72, wmma::mem_row_major);
    wmma::store_matrix_sync(&sC[wm * 32 + 16][wn * 16], acc[1], 72, wmma::mem_row_major);
    __syncthreads();

    #pragma unroll
    for (int it = 0; it < 16; ++it) {
        int idx = it * 256 + tid;
        int r = idx >> 6, c = idx & 63;
        float v = sC[r][c];
        if (bias) v += bias[n0 + c];
        if (mode == 0) {
            C[(size_t)(m0 + r) * ldC + n0 + c] = v;
        } else {
            // Head-flat store (proven round-1 / round-10 permute index math).
            const int nb = n0 + c;
            C[(size_t)(nb >> 6) * (Ss * Hd) + (size_t)(m0 + r) * Hd + (nb & 63)] = v;
        }
    }
}

// ---------------------------------------------------------------------------
// wmma split-bf16 scores: P[q,k] = 0.125 * dot(Q1[q,:], K1[k,:]) - slope*|q-k|
// MMA path byte-identical to the validated kernel; proven epilogue math.
// ---------------------------------------------------------------------------
__global__ void __launch_bounds__(256) wsplit_scores(
    const float* __restrict__ slopes, float* __restrict__ P)
{
    __shared__ __align__(128) __nv_bfloat16 sAh[64][40];
    __shared__ __align__(128) __nv_bfloat16 sAl[64][40];
    __shared__ __align__(128) __nv_bfloat16 sBh[64][40];
    __shared__ __align__(128) __nv_bfloat16 sBl[64][40];
    __shared__ __align__(128) float sC[64][72];

    const int tid = threadIdx.x, wid = tid >> 5;
    const int wm = wid & 1, wn = wid >> 1;
    const int m0 = blockIdx.y * 64, n0 = blockIdx.x * 64;
    const float* A = g_Q1 + (size_t)blockIdx.z * Ss * Hd;
    const float* B = g_K1 + (size_t)blockIdx.z * Ss * Hd;
    float* Pb = P + (size_t)blockIdx.z * Ss * Ss;

    const int lrow = tid >> 2, lcb = (tid & 3) * 8;

    wmma::fragment<wmma::accumulator, 16, 16, 16, float> acc[2];
    wmma::fill_fragment(acc[0], 0.0f);
    wmma::fill_fragment(acc[1], 0.0f);

    for (int k0 = 0; k0 < Hd; k0 += 32) {
        const float* ga = A + (size_t)(m0 + lrow) * Hd + k0 + lcb;
        const float* gb = B + (size_t)(n0 + lrow) * Hd + k0 + lcb;
        #pragma unroll
        for (int j = 0; j < 8; j += 4) {
            float4 va = *(const float4*)(ga + j);
            float4 vb = *(const float4*)(gb + j);
            float av[4] = {va.x, va.y, va.z, va.w};
            float bv[4] = {vb.x, vb.y, vb.z, vb.w};
            #pragma unroll
            for (int u = 0; u < 4; ++u) {
                __nv_bfloat16 ha = __float2bfloat16(av[u]);
                sAh[lrow][lcb + j + u] = ha;
                sAl[lrow][lcb + j + u] = __float2bfloat16(av[u] - __bfloat162float(ha));
                __nv_bfloat16 hb = __float2bfloat16(bv[u]);
                sBh[lrow][lcb + j + u] = hb;
                sBl[lrow][lcb + j + u] = __float2bfloat16(bv[u] - __bfloat162float(hb));
            }
        }
        __syncthreads();

        #pragma unroll
        for (int p = 0; p < 3; ++p) {
            const __nv_bfloat16 (*aS)[40] = (p == 2) ? sAl : sAh;
            const __nv_bfloat16 (*bS)[40] = (p == 1) ? sBl : sBh;
            #pragma unroll
            for (int kk = 0; kk < 32; kk += 16) {
                wmma::fragment<wmma::matrix_a, 16, 16, 16, __nv_bfloat16, wmma::row_major> af;
                wmma::fragment<wmma::matrix_b, 16, 16, 16, __nv_bfloat16, wmma::col_major> bf;
                wmma::load_matrix_sync(bf, &bS[wn * 16][kk], 40);
                #pragma unroll
                for (int i = 0; i < 2; ++i) {
                    wmma::load_matrix_sync(af, &aS[wm * 32 + i * 16][kk], 40);
                    wmma::mma_sync(acc[i], af, bf, acc[i]);
                }
            }
        }
        __syncthreads();
    }

    wmma::store_matrix_sync(&sC[wm * 32][wn * 16], acc[0], 72, wmma::mem_row_major);
    wmma::store_matrix_sync(&sC[wm * 32 + 16][wn * 16], acc[1], 72, wmma::mem_row_major);
    __syncthreads();

    const float slope = slopes[1];
    #pragma unroll
    for (int it = 0; it < 16; ++it) {
        int idx = it * 256 + tid;
        int r = idx >> 6, c = idx & 63;
        const int q = m0 + r, kk = n0 + c;
        Pb[(size_t)q * Ss + kk] = sC[r][c] * 0.125f - slope * fabsf((float)(q - kk));
    }
}

// ---------------------------------------------------------------------------
// Head-aware V transpose (VALIDATED round 10): Vt[b][h*64+d][k] = V[b,h,k,d]
// where V[b,h,k,d] = Vflat[b][h*Ss*Hd + k*Hd + d].
// ---------------------------------------------------------------------------
__global__ void transpose_vh(const float* __restrict__ in, float* __restrict__ outT)
{
    __shared__ float t[32][33];
    const int b = blockIdx.z >> 4, h = blockIdx.z & 15;
    const int k0 = blockIdx.x * 32, d0 = blockIdx.y * 32;
    const int tx = threadIdx.x, ty = threadIdx.y;
    const float* src = in + (size_t)b * Ss * Ee + (size_t)h * Ss * Hd;  // (k, d), ld = Hd
    float* dst = outT + (size_t)b * Ee * Ss + (size_t)h * Hd * Ss;      // (d, k), ld = Ss
    #pragma unroll
    for (int i = 0; i < 32; i += 8)
        t[ty + i][tx] = src[(size_t)(k0 + ty + i) * Hd + d0 + tx];
    __syncthreads();
    #pragma unroll
    for (int i = 0; i < 32; i += 8)
        dst[(size_t)(d0 + ty + i) * Ss + k0 + tx] = t[tx][ty + i];
}

// ------------------------- softmax (round-1 proven) --------------------------
__global__ void softmax_kernel(float* __restrict__ P)
{
    float* r = P + (long)blockIdx.y * Ss * Ss + (long)blockIdx.x * Ss;
    const int tid = threadIdx.x;
    __shared__ float red[256];

    float vals[8];
    float m = -1e30f;
    #pragma unroll
    for (int i = 0; i < 8; i++) {
        vals[i] = r[tid + i * 256];
        m = fmaxf(m, vals[i]);
    }
    red[tid] = m;
    __syncthreads();
    for (int s = 128; s > 0; s >>= 1) {
        if (tid < s) red[tid] = fmaxf(red[tid], red[tid + s]);
        __syncthreads();
    }
    m = red[0];
    __syncthreads();

    float sum = 0.f;
    #pragma unroll
    for (int i = 0; i < 8; i++) {
        vals[i] = __expf(vals[i] - m);
        sum += vals[i];
    }
    red[tid] = sum;
    __syncthreads();
    for (int s = 128; s > 0; s >>= 1) {
        if (tid < s) red[tid] += red[tid + s];
        __syncthreads();
    }
    const float inv = 1.f / red[0];
    #pragma unroll
    for (int i = 0; i < 8; i++)
        r[tid + i * 256] = vals[i] * inv;
}

// ---------------------------------------------------------------------------
extern "C" void kernel_launch(void* const* d_in, const int* in_sizes, int n_in,
                              void* d_out, int out_size)
{
    const float* x      = (const float*)d_in[0];
    const float* Wq     = (const float*)d_in[1];
    const float* bq     = (const float*)d_in[2];
    const float* Wk     = (const float*)d_in[3];
    const float* bk     = (const float*)d_in[4];
    const float* Wv     = (const float*)d_in[5];
    const float* bv     = (const float*)d_in[6];
    const float* Wo     = (const float*)d_in[7];
    const float* bo     = (const float*)d_in[8];
    const float* slopes = (const float*)d_in[9];

    float* out = (float*)d_out;                 // (B, S, E)
    float* P   = out + (long)Bb * Ss * Ee;      // probs1 (B, 1, S, S), computed in place

    float *pQ1, *pK1, *pV, *pVt, *pAttn;
    cudaGetSymbolAddress((void**)&pQ1, g_Q1);
    cudaGetSymbolAddress((void**)&pK1, g_K1);
    cudaGetSymbolAddress((void**)&pV, g_V);
    cudaGetSymbolAddress((void**)&pVt, g_Vt);
    cudaGetSymbolAddress((void**)&pAttn, g_attn);

    // Head-1 Q/K projections: rows 128..255 per batch of x @ W^T (validated wmma).
    wsplit_gemm<<<dim3(Ee / 64, 128 / 64, Bb), 256>>>(
        x + 128 * Ee, (long)Ss * Ee, Wq, 0, pQ1, (long)128 * Ee, Ee, bq, Ee, 0);
    wsplit_gemm<<<dim3(Ee / 64, 128 / 64, Bb), 256>>>(
        x + 128 * Ee, (long)Ss * Ee, Wk, 0, pK1, (long)128 * Ee, Ee, bk, Ee, 0);

    // Head-1 scores + ALiBi via validated GEMM body (replaces 44us SIMT kernel).
    wsplit_scores<<<dim3(Ss / 64, Ss / 64, Bb), 256>>>(slopes, P);

    // Full V projection (launch #4 — positioned for the ncu capture window).
    wsplit_gemm<<<dim3(Ee / 64, Bb * Ss / 64, 1), 256>>>(
        x, 0, Wv, 0, pV, 0, Ee, bv, Ee, 0);

    // Softmax in place (directly into d_out probs region).
    softmax_kernel<<<dim3(Ss, Bb), 256>>>(P);

    // Head-aware transpose (validated round 10).
    transpose_vh<<<dim3(Ss / 32, Hd / 32, Bb * Hh), dim3(32, 8)>>>(pV, pVt);

    // PV on the validated NT GEMM, storing head-flat directly (mode 1):
    // g_attn[b][n>>6][q][n&63] = sum_k P[b,q,k] * Vt[b,n,k].
    wsplit_gemm<<<dim3(Ee / 64, Ss / 64, Bb), 256>>>(
        P, (long)Ss * Ss, pVt, (long)Ee * Ss, pAttn, (long)Ss * Ee, 0, nullptr, Ss, 1);

    // Output projection: attn_out.reshape(B*S, E) @ Wo^T (validated wmma).
    wsplit_gemm<<<dim3(Ee / 64, Bb * Ss / 64, 1), 256>>>(
        pAttn, 0, Wo, 0, out, 0, Ee, bo, Ee, 0);
}